// round 11
// baseline (speedup 1.0000x reference)
#include <cuda_runtime.h>
#include <cuda_fp16.h>
#include <cstdint>

#define BATCH 8
#define NNODE 2048
#define NEDGE 65536
#define HDIM  128
#define NRAD  6
#define TILE_E 64

typedef unsigned long long u64;

// ---------------- device globals (no allocation) ----------------
// W3 A-fragments, fp16, 9 k-tiles: kt 0..7 = lin_w[:,256:384] (k=0..127);
// kt 8 = augmented node-term tile:
//   A channels per o: [u1h,u1l, u1h,u2h, u2l,u2h, ch,cl, 0...]
//   B channels per e: [xih,xih, xil,xjh, xjh,xjl, 1,1, 0...]
//   -> contributes xi*u1 + xj*u2 + c (residual ~2^-22).
__device__ uint4 g_WA[8 * 9 * 32];

// ---------------- smem byte offsets ----------------
#define OFF_B    0        // r fp16 B-fragments (swizzled): 16384 B
#define OFF_B8   16384    // augmented-tile B words, 16B/edge: 1024 B
#define OFF_RBF  17408    // rbf tile [64][8] f32 (padded): 2048 B
#define SMEM_BYTES 19456

// ---------------- helpers ----------------
__device__ __forceinline__ uint32_t smem_u32(const void* p) {
    uint32_t a;
    asm("{ .reg .u64 t; cvta.to.shared.u64 t, %1; cvt.u32.u64 %0, t; }" : "=r"(a) : "l"(p));
    return a;
}
__device__ __forceinline__ uint4 lds128(uint32_t addr) {
    uint4 v;
    asm volatile("ld.shared.v4.b32 {%0,%1,%2,%3}, [%4];"
                 : "=r"(v.x), "=r"(v.y), "=r"(v.z), "=r"(v.w) : "r"(addr));
    return v;
}
__device__ __forceinline__ uint32_t lds32(uint32_t addr) {
    uint32_t v;
    asm volatile("ld.shared.b32 %0, [%1];" : "=r"(v) : "r"(addr));
    return v;
}
__device__ __forceinline__ void sts64(uint32_t addr, u64 v) {
    asm volatile("st.shared.b64 [%0], %1;" :: "r"(addr), "l"(v) : "memory");
}
__device__ __forceinline__ void sts128(uint32_t addr, uint32_t a, uint32_t b,
                                       uint32_t c, uint32_t d) {
    asm volatile("st.shared.v4.b32 [%0], {%1,%2,%3,%4};"
                 :: "r"(addr), "r"(a), "r"(b), "r"(c), "r"(d) : "memory");
}
// packed f16x2: low half <- lo, high half <- hi
__device__ __forceinline__ uint32_t cvt_f16x2(float lo, float hi) {
    uint32_t d;
    asm("cvt.rn.f16x2.f32 %0, %2, %1;" : "=r"(d) : "f"(lo), "f"(hi));
    return d;
}
__device__ __forceinline__ void mma16816(float* d, uint32_t a0, uint32_t a1,
                                         uint32_t a2, uint32_t a3,
                                         uint32_t b0, uint32_t b1) {
    asm volatile(
        "mma.sync.aligned.m16n8k16.row.col.f32.f16.f16.f32 "
        "{%0,%1,%2,%3}, {%4,%5,%6,%7}, {%8,%9}, {%0,%1,%2,%3};"
        : "+f"(d[0]), "+f"(d[1]), "+f"(d[2]), "+f"(d[3])
        : "r"(a0), "r"(a1), "r"(a2), "r"(a3), "r"(b0), "r"(b1));
}
// silu via single-MUFU tanh: z*sigmoid(z) = 0.5z + 0.5z*tanh(0.5z)
__device__ __forceinline__ float silu_t(float z) {
    float h = 0.5f * z;
    float t;
    asm("tanh.approx.f32 %0, %1;" : "=f"(t) : "f"(h));
    return fmaf(h, t, h);
}

// ---------------------------------------------------------------------------
// Precompute: grid=16, block=256. One kernel, fully parallel.
//   blocks 0..7 : pack regular A-tiles (kt 0..7)       -> 2048 entries
//   blocks 8..15: block (8+tm): warp-parallel u/c for o in [tm*16, tm*16+16),
//                 then 32 threads pack the aug tile for that tm.
// ---------------------------------------------------------------------------
__global__ void precompute_all(const float* __restrict__ emb_w,
                               const float* __restrict__ emb_b,
                               const float* __restrict__ lin_w,
                               const float* __restrict__ lin_b) {
    const int tid = threadIdx.x;
    const int bid = blockIdx.x;

    if (bid < 8) {
        const int idx  = bid * 256 + tid;          // 0..2047
        const int lane = idx & 31;
        const int t    = idx >> 5;                 // 0..63
        const int kt   = t & 7;
        const int tm   = t >> 3;
        const int o0 = tm * 16 + (lane >> 2);
        const int o1 = o0 + 8;
        const int q  = lane & 3;
        const int k0 = kt * 16 + q * 2;
        const float* base = lin_w + 2 * HDIM;
        uint32_t a0 = cvt_f16x2(base[o0 * (3 * HDIM) + k0],     base[o0 * (3 * HDIM) + k0 + 1]);
        uint32_t a1 = cvt_f16x2(base[o1 * (3 * HDIM) + k0],     base[o1 * (3 * HDIM) + k0 + 1]);
        uint32_t a2 = cvt_f16x2(base[o0 * (3 * HDIM) + k0 + 8], base[o0 * (3 * HDIM) + k0 + 9]);
        uint32_t a3 = cvt_f16x2(base[o1 * (3 * HDIM) + k0 + 8], base[o1 * (3 * HDIM) + k0 + 9]);
        g_WA[(tm * 9 + kt) * 32 + lane] = make_uint4(a0, a1, a2, a3);
    } else {
        const int tm = bid - 8;
        __shared__ float su[16][4];                // u1, u2, c per local o
        const int w    = tid >> 5;
        const int lane = tid & 31;
        #pragma unroll
        for (int r = 0; r < 2; ++r) {
            const int o = tm * 16 + w * 2 + r;
            const float* row = lin_w + o * (3 * HDIM);
            float u1 = 0.f, u2 = 0.f, cc = 0.f;
            #pragma unroll
            for (int s = 0; s < 4; ++s) {
                const int h = lane + s * 32;
                float w1 = row[h], w2 = row[HDIM + h];
                float ew = emb_w[h], eb = emb_b[h];
                u1 = fmaf(w1, ew, u1);
                u2 = fmaf(w2, ew, u2);
                cc = fmaf(w1 + w2, eb, cc);
            }
            #pragma unroll
            for (int s = 16; s > 0; s >>= 1) {
                u1 += __shfl_down_sync(0xffffffff, u1, s);
                u2 += __shfl_down_sync(0xffffffff, u2, s);
                cc += __shfl_down_sync(0xffffffff, cc, s);
            }
            if (lane == 0) {
                su[w * 2 + r][0] = u1;
                su[w * 2 + r][1] = u2;
                su[w * 2 + r][2] = cc + lin_b[o];
            }
        }
        __syncthreads();
        if (tid < 32) {
            const int q = tid & 3;
            uint32_t a[2];
            #pragma unroll
            for (int r = 0; r < 2; ++r) {
                const int ol = (tid >> 2) + r * 8;
                float u1 = su[ol][0], u2 = su[ol][1], cc = su[ol][2];
                float u1h = __half2float(__float2half_rn(u1));
                float u2h = __half2float(__float2half_rn(u2));
                float chf = __half2float(__float2half_rn(cc));
                float u1l = u1 - u1h, u2l = u2 - u2h, clf = cc - chf;
                uint32_t wv;
                if      (q == 0) wv = cvt_f16x2(u1h, u1l);
                else if (q == 1) wv = cvt_f16x2(u1h, u2h);
                else if (q == 2) wv = cvt_f16x2(u2l, u2h);
                else             wv = cvt_f16x2(chf, clf);
                a[r] = wv;
            }
            g_WA[(tm * 9 + 8) * 32 + tid] = make_uint4(a[0], a[1], 0u, 0u);
        }
    }
}

// ---------------------------------------------------------------------------
// Main fused kernel: 1 CTA = 64 edges x 128 outputs, warp tile 32o x 32e,
// 3 CTAs/SM (regs capped at 85 by launch bounds). Node terms folded via
// augmented k-tile; B layout kt-paired + parity swizzle (as validated in R8).
// ---------------------------------------------------------------------------
__global__ void __launch_bounds__(256, 3)
edge_mlp_kernel(const float* __restrict__ x,
                const float* __restrict__ rbf,
                const int* __restrict__ iidx,
                const int* __restrict__ jidx,
                const float* __restrict__ rbf_w,
                const float* __restrict__ rbf_b,
                float* __restrict__ out) {
    extern __shared__ char sm[];
    const uint32_t sb = smem_u32(sm);

    const int b    = blockIdx.y;
    const int e0   = blockIdx.x * TILE_E;
    const int tid  = threadIdx.x;
    const int wid  = tid >> 5;
    const int lane = tid & 31;

    float* rbf_s = (float*)(sm + OFF_RBF);   // [64][8] padded

    // ---- stage rbf tile (384 floats) into padded rows [e][8] ----
    {
        const float* src = rbf + ((size_t)b * NEDGE + e0) * NRAD;
        if (tid < 384) {
            int e = tid / NRAD, m = tid - e * NRAD;
            rbf_s[e * 8 + m] = src[tid];
        }
        int idx = tid + 256;
        if (idx < 384) {
            int e = idx / NRAD, m = idx - e * NRAD;
            rbf_s[e * 8 + m] = src[idx];
        }
    }
    // ---- gather x_i/x_j, build augmented B words (16B/edge) ----
    if (tid < TILE_E) {
        int e = e0 + tid;
        int ii = iidx[e] & (NNODE - 1);
        int jj = jidx[e] & (NNODE - 1);
        float xi = x[b * NNODE + ii];
        float xj = x[b * NNODE + jj];
        float xih = __half2float(__float2half_rn(xi));
        float xjh = __half2float(__float2half_rn(xj));
        float xil = xi - xih, xjl = xj - xjh;
        uint32_t w0 = cvt_f16x2(xi, xi);      // (xih, xih)
        uint32_t w1 = cvt_f16x2(xil, xj);     // (xil, xjh)
        uint32_t w2 = cvt_f16x2(xj, xjl);     // (xjh, xjl)
        uint32_t w3 = 0x3C003C00u;            // (1, 1)
        sts128(sb + OFF_B8 + (uint32_t)tid * 16, w0, w1, w2, w3);
    }
    __syncthreads();

    // ---- r-phase: lane owns 4 k-channels; warp handles 8 edges ----
    {
        const int kt = lane >> 2;        // 0..7
        const int q  = lane & 3;         // 0..3
        const int p  = kt >> 1;          // pair 0..3
        const int ph = kt & 1;
        const uint32_t swz = (uint32_t)((p & 1) << 6);
        const int kb = kt * 16 + q * 2;
        const int ks[4] = { kb, kb + 1, kb + 8, kb + 9 };

        float rw[4][NRAD], rb4[4];
        #pragma unroll
        for (int kk = 0; kk < 4; ++kk) {
            rb4[kk] = __ldg(rbf_b + ks[kk]);
            #pragma unroll
            for (int m = 0; m < NRAD; ++m)
                rw[kk][m] = __ldg(rbf_w + ks[kk] * NRAD + m);
        }

        #pragma unroll 2
        for (int t = 0; t < 8; ++t) {
            const int e = wid * 8 + t;
            const float4 r03 = *(const float4*)(rbf_s + e * 8);
            const float2 r45 = *(const float2*)(rbf_s + e * 8 + 4);
            const float rv[NRAD] = { r03.x, r03.y, r03.z, r03.w, r45.x, r45.y };

            float z[4];
            #pragma unroll
            for (int kk = 0; kk < 4; ++kk) {
                z[kk] = rb4[kk];
                #pragma unroll
                for (int m = 0; m < NRAD; ++m)
                    z[kk] = fmaf(rv[m], rw[kk][m], z[kk]);
            }
            uint32_t b01 = cvt_f16x2(silu_t(z[0]), silu_t(z[1]));
            uint32_t b23 = cvt_f16x2(silu_t(z[2]), silu_t(z[3]));

            const uint32_t C2 = (uint32_t)(wid * 4 + p);      // e>>3 == wid
            const uint32_t w  = (uint32_t)(t * 4 + q);        // e&7 == t
            uint32_t addr = sb + OFF_B + C2 * 512 + ((w * 16) ^ swz) + ph * 8;
            sts64(addr, (u64)b01 | ((u64)b23 << 32));
        }
    }
    __syncthreads();

    // ---- mma: warp tile 32(o) x 32(e); LDS.128 feeds two MMAs ----
    const int wm  = wid & 3;    // o-group: rows wm*32..+31
    const int wng = wid >> 2;   // e-group: cols wng*32..+31

    float acc[2][4][4];
    #pragma unroll
    for (int i = 0; i < 2; ++i)
        #pragma unroll
        for (int j = 0; j < 4; ++j)
            #pragma unroll
            for (int q = 0; q < 4; ++q) acc[i][j][q] = 0.f;

    #pragma unroll
    for (int p = 0; p < 4; ++p) {
        const int kt0 = 2 * p, kt1 = 2 * p + 1;
        uint4 a0e = __ldg(g_WA + ((wm * 2 + 0) * 9 + kt0) * 32 + lane);
        uint4 a0o = __ldg(g_WA + ((wm * 2 + 0) * 9 + kt1) * 32 + lane);
        uint4 a1e = __ldg(g_WA + ((wm * 2 + 1) * 9 + kt0) * 32 + lane);
        uint4 a1o = __ldg(g_WA + ((wm * 2 + 1) * 9 + kt1) * 32 + lane);
        const uint32_t swz = (uint32_t)((p & 1) << 6);
        #pragma unroll
        for (int j = 0; j < 4; ++j) {
            const uint32_t C2 = (uint32_t)(((wng * 4 + j) * 4 + p));
            uint4 v = lds128(sb + OFF_B + C2 * 512 + (((uint32_t)lane * 16) ^ swz));
            mma16816(acc[0][j], a0e.x, a0e.y, a0e.z, a0e.w, v.x, v.y);
            mma16816(acc[0][j], a0o.x, a0o.y, a0o.z, a0o.w, v.z, v.w);
            mma16816(acc[1][j], a1e.x, a1e.y, a1e.z, a1e.w, v.x, v.y);
            mma16816(acc[1][j], a1o.x, a1o.y, a1o.z, a1o.w, v.z, v.w);
        }
    }
    // ---- augmented tile (node terms): a2/a3 = 0, b1 = 0 ----
    {
        uint4 ax0 = __ldg(g_WA + ((wm * 2 + 0) * 9 + 8) * 32 + lane);
        uint4 ax1 = __ldg(g_WA + ((wm * 2 + 1) * 9 + 8) * 32 + lane);
        #pragma unroll
        for (int j = 0; j < 4; ++j) {
            uint32_t b0 = lds32(sb + OFF_B8 +
                (uint32_t)((((wng * 4 + j) * 8 + (lane >> 2)) * 16) + (lane & 3) * 4));
            mma16816(acc[0][j], ax0.x, ax0.y, 0u, 0u, b0, 0u);
            mma16816(acc[1][j], ax1.x, ax1.y, 0u, 0u, b0, 0u);
        }
    }

    // ---- epilogue: silu + store (node terms already in acc) ----
    float* outb = out + ((size_t)b * NEDGE + e0) * HDIM;
    #pragma unroll
    for (int j = 0; j < 4; ++j) {
        const int eb = wng * 32 + j * 8 + (lane & 3) * 2;
        #pragma unroll
        for (int i = 0; i < 2; ++i) {
            const int ob = wm * 32 + i * 16 + (lane >> 2);
            #pragma unroll
            for (int h = 0; h < 2; ++h) {           // o vs o+8
                const int oo = ob + h * 8;
                outb[(size_t)eb * HDIM + oo]       = silu_t(acc[i][j][h * 2 + 0]);
                outb[(size_t)(eb + 1) * HDIM + oo] = silu_t(acc[i][j][h * 2 + 1]);
            }
        }
    }
}

// ---------------------------------------------------------------------------
extern "C" void kernel_launch(void* const* d_in, const int* in_sizes, int n_in,
                              void* d_out, int out_size) {
    const float* x     = (const float*)d_in[0];
    const float* rbf   = (const float*)d_in[1];
    const int*   iidx  = (const int*)d_in[2];   // int32 (JAX x64 disabled)
    const int*   jidx  = (const int*)d_in[3];
    const float* emb_w = (const float*)d_in[4];
    const float* emb_b = (const float*)d_in[5];
    const float* rbf_w = (const float*)d_in[6];
    const float* rbf_b = (const float*)d_in[7];
    const float* lin_w = (const float*)d_in[8];
    const float* lin_b = (const float*)d_in[9];
    float* out = (float*)d_out;

    precompute_all<<<16, 256>>>(emb_w, emb_b, lin_w, lin_b);

    cudaFuncSetAttribute(edge_mlp_kernel,
                         cudaFuncAttributeMaxDynamicSharedMemorySize, SMEM_BYTES);
    dim3 grid(NEDGE / TILE_E, BATCH);   // (1024, 8)
    edge_mlp_kernel<<<grid, 256, SMEM_BYTES>>>(x, rbf, iidx, jidx, rbf_w, rbf_b, out);
}

// round 12
// speedup vs baseline: 1.5277x; 1.5277x over previous
#include <cuda_runtime.h>
#include <cuda_fp16.h>
#include <cstdint>

#define BATCH 8
#define NNODE 2048
#define NEDGE 65536
#define HDIM  128
#define NRAD  6
#define TILE_E 128

typedef unsigned long long u64;

// ---------------- device globals (no allocation) ----------------
// GEMM-2 B fragments (W fp16, single term) + aug node-term tile (kt=8):
//   g_WB[(j*9 + kt)*32 + lane] : low32 = b0, high32 = b1 (b1=0 for kt=8)
//   kt<8 : b0 = {W[o][k0], W[o][k0+1]}, b1 = {W[o][k0+8], W[o][k0+9]},
//          o = j*8 + (lane>>2), k0 = kt*16 + (lane&3)*2, W[o][k] = lin_w[o][256+k]
//   kt=8 : channel pairs by lane&3: (u1h,u1l),(u1h,u2h),(u2l,u2h),(ch,cl)
__device__ u64 g_WB[16 * 9 * 32];
// GEMM-1 B fragments (rbf_w 2-term hi/lo, bias in channel m=6):
//   g_RW[j*32 + lane] : low32 = hi-term b0, high32 = lo-term b0 (b1 = 0)
__device__ u64 g_RW[16 * 32];

// ---------------- helpers ----------------
__device__ __forceinline__ uint32_t cvt_f16x2(float lo, float hi) {
    uint32_t d;
    asm("cvt.rn.f16x2.f32 %0, %2, %1;" : "=r"(d) : "f"(lo), "f"(hi));
    return d;
}
__device__ __forceinline__ void mma16816(float* d, uint32_t a0, uint32_t a1,
                                         uint32_t a2, uint32_t a3,
                                         uint32_t b0, uint32_t b1) {
    asm volatile(
        "mma.sync.aligned.m16n8k16.row.col.f32.f16.f16.f32 "
        "{%0,%1,%2,%3}, {%4,%5,%6,%7}, {%8,%9}, {%0,%1,%2,%3};"
        : "+f"(d[0]), "+f"(d[1]), "+f"(d[2]), "+f"(d[3])
        : "r"(a0), "r"(a1), "r"(a2), "r"(a3), "r"(b0), "r"(b1));
}
// silu via single-MUFU tanh: z*sigmoid(z) = 0.5z + 0.5z*tanh(0.5z)
__device__ __forceinline__ float silu_t(float z) {
    float h = 0.5f * z;
    float t;
    asm("tanh.approx.f32 %0, %1;" : "=f"(t) : "f"(h));
    return fmaf(h, t, h);
}
__device__ __forceinline__ float h16(float v) {
    return __half2float(__float2half_rn(v));
}
// aug A fragment for one edge: channels by q = lane&3:
// 0:(xih,xih) 1:(xil,xjh) 2:(xjh,xjl) 3:(1,1)
__device__ __forceinline__ uint32_t aug_frag(float xi, float xj, int q) {
    if (q == 0) return cvt_f16x2(xi, xi);
    if (q == 1) return cvt_f16x2(xi - h16(xi), xj);
    if (q == 2) return cvt_f16x2(xj, xj - h16(xj));
    return 0x3C003C00u;
}

// ---------------------------------------------------------------------------
// Single precompute kernel, grid=26, block=256 (2 launches/replay total).
//   bid 0..15 : g_WB kt 0..7  (4096 entries)
//   bid 16..23: u1/u2/c (warp-parallel reduce) + aug tile for o block
//   bid 24..25: g_RW (512 entries)
// ---------------------------------------------------------------------------
__global__ void precompute_all(const float* __restrict__ emb_w,
                               const float* __restrict__ emb_b,
                               const float* __restrict__ rbf_w,
                               const float* __restrict__ rbf_b,
                               const float* __restrict__ lin_w,
                               const float* __restrict__ lin_b) {
    const int tid = threadIdx.x;
    const int bid = blockIdx.x;

    if (bid < 16) {
        const int idx  = bid * 256 + tid;        // 0..4095
        const int lane = idx & 31;
        const int t    = idx >> 5;               // 0..127
        const int kt   = t & 7;
        const int j    = t >> 3;
        const int o  = j * 8 + (lane >> 2);
        const int k0 = kt * 16 + (lane & 3) * 2;
        const float* wrow = lin_w + o * (3 * HDIM) + 2 * HDIM;
        uint32_t b0 = cvt_f16x2(wrow[k0],     wrow[k0 + 1]);
        uint32_t b1 = cvt_f16x2(wrow[k0 + 8], wrow[k0 + 9]);
        g_WB[(j * 9 + kt) * 32 + lane] = (u64)b0 | ((u64)b1 << 32);
    } else if (bid < 24) {
        const int t = bid - 16;                  // o block [16t, 16t+16)
        __shared__ float su[16][3];
        const int w    = tid >> 5;
        const int lane = tid & 31;
        #pragma unroll
        for (int r = 0; r < 2; ++r) {
            const int o = t * 16 + w * 2 + r;
            const float* row = lin_w + o * (3 * HDIM);
            float u1 = 0.f, u2 = 0.f, cc = 0.f;
            #pragma unroll
            for (int s = 0; s < 4; ++s) {
                const int h = lane + s * 32;
                float w1 = row[h], w2 = row[HDIM + h];
                float ew = emb_w[h], eb = emb_b[h];
                u1 = fmaf(w1, ew, u1);
                u2 = fmaf(w2, ew, u2);
                cc = fmaf(w1 + w2, eb, cc);
            }
            #pragma unroll
            for (int s = 16; s > 0; s >>= 1) {
                u1 += __shfl_down_sync(0xffffffff, u1, s);
                u2 += __shfl_down_sync(0xffffffff, u2, s);
                cc += __shfl_down_sync(0xffffffff, cc, s);
            }
            if (lane == 0) {
                su[w * 2 + r][0] = u1;
                su[w * 2 + r][1] = u2;
                su[w * 2 + r][2] = cc + lin_b[o];
            }
        }
        __syncthreads();
        if (tid < 64) {
            const int lane2 = tid & 31;
            const int j  = t * 2 + (tid >> 5);
            const int ol = (j * 8 + (lane2 >> 2)) - t * 16;   // 0..15
            const int q  = lane2 & 3;
            float u1 = su[ol][0], u2 = su[ol][1], cc = su[ol][2];
            float u1h = h16(u1), u2h = h16(u2), chf = h16(cc);
            float u1l = u1 - u1h, u2l = u2 - u2h, clf = cc - chf;
            uint32_t b0;
            if      (q == 0) b0 = cvt_f16x2(u1h, u1l);
            else if (q == 1) b0 = cvt_f16x2(u1h, u2h);
            else if (q == 2) b0 = cvt_f16x2(u2l, u2h);
            else             b0 = cvt_f16x2(chf, clf);
            g_WB[(j * 9 + 8) * 32 + lane2] = (u64)b0;
        }
    } else {
        const int idx = (bid - 24) * 256 + tid;  // 0..511
        if (idx < 16 * 32) {
            const int lane = idx & 31;
            const int j = idx >> 5;
            const int n = j * 8 + (lane >> 2);
            const int q = lane & 3;
            float f0, f1;
            if (q == 3) { f0 = rbf_b[n]; f1 = 0.f; }
            else        { f0 = rbf_w[n * NRAD + q * 2]; f1 = rbf_w[n * NRAD + q * 2 + 1]; }
            float f0h = h16(f0), f1h = h16(f1);
            uint32_t bh = cvt_f16x2(f0h, f1h);
            uint32_t bl = cvt_f16x2(f0 - f0h, f1 - f1h);
            g_RW[idx] = (u64)bh | ((u64)bl << 32);
        }
    }
}

// ---------------------------------------------------------------------------
// Main fused kernel: barrier-free, smem-free. Each warp owns 16 edges.
//   GEMM-1: Z[16e][128ch] = rbf @ rbf_w.T + b   (fp16 MMA, 2-term weights)
//   silu + cvt (register-only fragment chaining)
//   GEMM-2: out[16e][128o] = r @ W.T (+ node terms via aug k-tile)
//   Epilogue: silu + STG.64 (warp owns complete e-rows; 32B sectors)
// ---------------------------------------------------------------------------
__global__ void __launch_bounds__(256, 2)
edge_mlp_kernel(const float* __restrict__ x,
                const float* __restrict__ rbf,
                const int* __restrict__ iidx,
                const int* __restrict__ jidx,
                float* __restrict__ out) {
    const int b    = blockIdx.y;
    const int e0   = blockIdx.x * TILE_E;
    const int tid  = threadIdx.x;
    const int wid  = tid >> 5;
    const int lane = tid & 31;
    const int q    = lane & 3;

    const int e_lo = e0 + wid * 16 + (lane >> 2);
    const int e_hi = e_lo + 8;

    // ---- GEMM-1 A fragments: rbf channels (m0, m0+1); q==3 -> bias ch (1,0)
    uint32_t a0, a1;
    if (q == 3) {
        a0 = a1 = 0x00003C00u;     // (1.0, 0.0)
    } else {
        const int m0 = q * 2;
        const float2 rl = *(const float2*)(rbf + ((size_t)b * NEDGE + e_lo) * NRAD + m0);
        const float2 rh = *(const float2*)(rbf + ((size_t)b * NEDGE + e_hi) * NRAD + m0);
        a0 = cvt_f16x2(rl.x, rl.y);
        a1 = cvt_f16x2(rh.x, rh.y);
    }

    // ---- aug A fragments (node terms; int32 indices, masked) ----
    uint32_t ax0, ax1;
    {
        int il = iidx[e_lo] & (NNODE - 1), jl = jidx[e_lo] & (NNODE - 1);
        int ih = iidx[e_hi] & (NNODE - 1), jh = jidx[e_hi] & (NNODE - 1);
        float xiL = x[b * NNODE + il], xjL = x[b * NNODE + jl];
        float xiH = x[b * NNODE + ih], xjH = x[b * NNODE + jh];
        ax0 = aug_frag(xiL, xjL, q);
        ax1 = aug_frag(xiH, xjH, q);
    }

    // ---- GEMM-1: Z = rbf @ rbf_w.T + b (16 independent acc chains) ----
    float z[16][4];
    #pragma unroll
    for (int j = 0; j < 16; ++j)
        #pragma unroll
        for (int c = 0; c < 4; ++c) z[j][c] = 0.f;

    #pragma unroll
    for (int j = 0; j < 16; ++j) {
        u64 wv = __ldg(g_RW + j * 32 + lane);
        mma16816(z[j], a0, a1, 0u, 0u, (uint32_t)wv, 0u);          // hi term
        mma16816(z[j], a0, a1, 0u, 0u, (uint32_t)(wv >> 32), 0u);  // lo term
    }

    // ---- silu + cvt: chain Z fragments into GEMM-2 A fragments ----
    uint32_t A2[8][4];
    #pragma unroll
    for (int kt = 0; kt < 8; ++kt) {
        A2[kt][0] = cvt_f16x2(silu_t(z[2 * kt][0]),     silu_t(z[2 * kt][1]));
        A2[kt][1] = cvt_f16x2(silu_t(z[2 * kt][2]),     silu_t(z[2 * kt][3]));
        A2[kt][2] = cvt_f16x2(silu_t(z[2 * kt + 1][0]), silu_t(z[2 * kt + 1][1]));
        A2[kt][3] = cvt_f16x2(silu_t(z[2 * kt + 1][2]), silu_t(z[2 * kt + 1][3]));
    }

    // ---- GEMM-2 in two o-halves (caps live registers) + epilogue ----
    const size_t rowLo = ((size_t)b * NEDGE + e_lo) * HDIM;
    const size_t rowHi = ((size_t)b * NEDGE + e_hi) * HDIM;

    #pragma unroll
    for (int half = 0; half < 2; ++half) {
        float acc[8][4];
        #pragma unroll
        for (int j = 0; j < 8; ++j)
            #pragma unroll
            for (int c = 0; c < 4; ++c) acc[j][c] = 0.f;

        #pragma unroll
        for (int kt = 0; kt < 8; ++kt) {
            #pragma unroll
            for (int j = 0; j < 8; ++j) {
                const int jj = half * 8 + j;
                u64 wv = __ldg(g_WB + (jj * 9 + kt) * 32 + lane);
                mma16816(acc[j], A2[kt][0], A2[kt][1], A2[kt][2], A2[kt][3],
                         (uint32_t)wv, (uint32_t)(wv >> 32));
            }
        }
        #pragma unroll
        for (int j = 0; j < 8; ++j) {
            const int jj = half * 8 + j;
            u64 av = __ldg(g_WB + (jj * 9 + 8) * 32 + lane);
            mma16816(acc[j], ax0, ax1, 0u, 0u, (uint32_t)av, 0u);

            const int o0 = jj * 8 + q * 2;
            float2 vlo = make_float2(silu_t(acc[j][0]), silu_t(acc[j][1]));
            float2 vhi = make_float2(silu_t(acc[j][2]), silu_t(acc[j][3]));
            *(float2*)(out + rowLo + o0) = vlo;
            *(float2*)(out + rowHi + o0) = vhi;
        }
    }
}

// ---------------------------------------------------------------------------
extern "C" void kernel_launch(void* const* d_in, const int* in_sizes, int n_in,
                              void* d_out, int out_size) {
    const float* x     = (const float*)d_in[0];
    const float* rbf   = (const float*)d_in[1];
    const int*   iidx  = (const int*)d_in[2];   // int32 (JAX x64 disabled)
    const int*   jidx  = (const int*)d_in[3];
    const float* emb_w = (const float*)d_in[4];
    const float* emb_b = (const float*)d_in[5];
    const float* rbf_w = (const float*)d_in[6];
    const float* rbf_b = (const float*)d_in[7];
    const float* lin_w = (const float*)d_in[8];
    const float* lin_b = (const float*)d_in[9];
    float* out = (float*)d_out;

    precompute_all<<<26, 256>>>(emb_w, emb_b, rbf_w, rbf_b, lin_w, lin_b);

    dim3 grid(NEDGE / TILE_E, BATCH);   // (512, 8)
    edge_mlp_kernel<<<grid, 256>>>(x, rbf, iidx, jidx, out);
}